// round 17
// baseline (speedup 1.0000x reference)
#include <cuda_runtime.h>
#include <cuda_fp16.h>
#include <math.h>

// Problem constants
#define NN 50000
#define EE 800000
#define NE 850000      // EE + NN self loops
#define FIN 32
#define CDIM 16
#define DIN 48
#define CC 64
#define H0 2

// ---------------- device scratch (allocation-free rule: __device__ globals) --------
__device__ __half g_h0h[NN * 128];    // layer0 node features, fp16 [N,2,64]
__device__ float g_as0[NN * 2];
__device__ float g_ad0[NN * 2];
__device__ __half g_h1h[NN * 64];     // layer1 input features, fp16
__device__ float g_as1[NN];
__device__ float g_ad1[NN];
// CSR build scratch
__device__ int g_cnt[NN];
__device__ int g_off[NN + 1];
__device__ int g_cur[NN];
__device__ int g_srcs[NE];

__device__ __forceinline__ unsigned h2u(__half2 v) { return *(unsigned*)&v; }

// ---------------- CSR build: histogram of dst -------------------------------------
__global__ void khist(const int* __restrict__ ei) {
    int e = blockIdx.x * blockDim.x + threadIdx.x;
    if (e >= NE) return;
    int dst = (e < EE) ? ei[EE + e] : (e - EE);
    atomicAdd(&g_cnt[dst], 1);
}

// ---------------- CSR build: exclusive scan (single block, 1024 threads) ----------
__global__ void __launch_bounds__(1024) kscan() {
    __shared__ int spart[1024];
    const int CH = (NN + 1023) / 1024;   // 49
    int t = threadIdx.x;
    int base = t * CH;
    int sum = 0;
    for (int i = 0; i < CH; ++i) {
        int b = base + i;
        if (b < NN) sum += g_cnt[b];
    }
    spart[t] = sum;
    __syncthreads();
    for (int o = 1; o < 1024; o <<= 1) {
        int v = (t >= o) ? spart[t - o] : 0;
        __syncthreads();
        spart[t] += v;
        __syncthreads();
    }
    int run = spart[t] - sum;           // exclusive prefix of this thread's chunk
    for (int i = 0; i < CH; ++i) {
        int b = base + i;
        if (b < NN) {
            g_off[b] = run;
            g_cur[b] = run;
            run += g_cnt[b];
        }
    }
    if (t == 1023) g_off[NN] = spart[1023];
}

// ---------------- CSR build: scatter src ids --------------------------------------
__global__ void kscatter(const int* __restrict__ ei) {
    int e = blockIdx.x * blockDim.x + threadIdx.x;
    if (e >= NE) return;
    int src, dst;
    if (e < EE) { src = ei[e]; dst = ei[EE + e]; }
    else        { src = dst = e - EE; }
    int pos = atomicAdd(&g_cur[dst], 1);
    g_srcs[pos] = src;
}

// ---------------- k1g: tiled GEMM  h0 = concat(base,emb) @ W0  + alpha epilogue ----
#define G1_M 64
__global__ void __launch_bounds__(256) k1g(const float* __restrict__ x,
                                           const float* __restrict__ emb,
                                           const float* __restrict__ W0,
                                           const float* __restrict__ aS0,
                                           const float* __restrict__ aD0) {
    __shared__ float sW[48][128];                 // 24 KB
    __shared__ __align__(16) float sXT[48][68];   // 12.75 KB, 16B-aligned rows
    int tid = threadIdx.x;
    int c = tid & 15, rm = tid >> 4;
    int base = blockIdx.x * G1_M;

    // stage W0 (48x128, row-major) -> sW
    {
        float4* dstp = (float4*)&sW[0][0];
        const float4* srcp = (const float4*)W0;
        #pragma unroll
        for (int r = 0; r < 6; ++r) dstp[tid + r * 256] = srcp[tid + r * 256];
    }
    // stage X tile transposed: sXT[k][m]
    #pragma unroll
    for (int r = 0; r < 12; ++r) {
        int idx = tid + r * 256;      // < 3072
        int m = idx / 48, k = idx - m * 48;
        int n = base + m;
        float v = 0.f;
        if (n < NN) {
            if (k < FIN) v = x[n * 33 + k];
            else {
                int cid = (int)x[n * 33 + FIN];
                v = emb[cid * CDIM + (k - FIN)];
            }
        }
        sXT[k][m] = v;
    }
    float aSr[8], aDr[8];
    #pragma unroll
    for (int j = 0; j < 8; ++j) { aSr[j] = aS0[c * 8 + j]; aDr[j] = aD0[c * 8 + j]; }
    __syncthreads();

    float acc[4][8];
    #pragma unroll
    for (int m = 0; m < 4; ++m)
        #pragma unroll
        for (int j = 0; j < 8; ++j) acc[m][j] = 0.f;

    #pragma unroll 8
    for (int k = 0; k < 48; ++k) {
        float4 wa = *(const float4*)&sW[k][c * 8];
        float4 wb = *(const float4*)&sW[k][c * 8 + 4];
        float4 xm4 = *(const float4*)&sXT[k][rm * 4];
        float xm[4] = {xm4.x, xm4.y, xm4.z, xm4.w};
        #pragma unroll
        for (int m = 0; m < 4; ++m) {
            acc[m][0] += xm[m] * wa.x;
            acc[m][1] += xm[m] * wa.y;
            acc[m][2] += xm[m] * wa.z;
            acc[m][3] += xm[m] * wa.w;
            acc[m][4] += xm[m] * wb.x;
            acc[m][5] += xm[m] * wb.y;
            acc[m][6] += xm[m] * wb.z;
            acc[m][7] += xm[m] * wb.w;
        }
    }

    int h = (c >> 3) & 1;             // this thread's cols are entirely in head h
    #pragma unroll
    for (int m = 0; m < 4; ++m) {
        int n = base + rm * 4 + m;
        float vs = 0.f, vd = 0.f;
        #pragma unroll
        for (int j = 0; j < 8; ++j) { vs += acc[m][j] * aSr[j]; vd += acc[m][j] * aDr[j]; }
        #pragma unroll
        for (int o = 4; o >= 1; o >>= 1) {
            vs += __shfl_xor_sync(0xffffffffu, vs, o);
            vd += __shfl_xor_sync(0xffffffffu, vd, o);
        }
        if (n < NN) {
            __half2 p0 = __floats2half2_rn(acc[m][0], acc[m][1]);
            __half2 p1 = __floats2half2_rn(acc[m][2], acc[m][3]);
            __half2 p2 = __floats2half2_rn(acc[m][4], acc[m][5]);
            __half2 p3 = __floats2half2_rn(acc[m][6], acc[m][7]);
            uint4 u;
            u.x = h2u(p0); u.y = h2u(p1); u.z = h2u(p2); u.w = h2u(p3);
            *(uint4*)&g_h0h[n * 128 + c * 8] = u;
            if ((tid & 7) == 0) {
                g_as0[n * 2 + h] = vs;
                g_ad0[n * 2 + h] = vd;
            }
        }
    }
}

// ---------------- kfused: layer0 aggregation + LN/ELU + GEMM W1 + alphas -----------
// Block: 256 thr, 64 dst nodes. Phase A: warp gathers 8 nodes (kagg0-style, in regs),
// normalizes, head-means, LayerNorms, ELUs -> sYT. Phase B: k4g-style GEMM.
#define GF_M 64
__global__ void __launch_bounds__(256) kfused(const float* __restrict__ b0,
                   const float* __restrict__ lng, const float* __restrict__ lnb,
                   const float* __restrict__ W1, const float* __restrict__ aS1,
                   const float* __restrict__ aD1) {
    __shared__ float sW1s[64][64];                // 16 KB
    __shared__ __align__(16) float sYT[64][68];   // 17 KB, LN(x) transposed
    int tid = threadIdx.x, w = tid >> 5, lane = tid & 31;
    int base = blockIdx.x * GF_M;

    // stage W1
    {
        float4* dstp = (float4*)&sW1s[0][0];
        const float4* srcp = (const float4*)W1;
        #pragma unroll
        for (int r = 0; r < 4; ++r) dstp[tid + r * 256] = srcp[tid + r * 256];
    }

    int half = lane >> 4;             // which of the 2 in-flight edges this lane serves
    int lc = lane & 15;               // col group within edge (cols lc*8..+7)
    int hsel = lc >> 3;               // 0: head0 cols, 1: head1 cols
    int jc = lc & 7;                  // 0..7: post-mean col group
    // LN params for cols jc*8..+7
    float b0r[8], gr[8], ber[8];
    #pragma unroll
    for (int j = 0; j < 8; j += 4) {
        *(float4*)&b0r[j] = *(const float4*)&b0[jc * 8 + j];
        *(float4*)&gr[j]  = *(const float4*)&lng[jc * 8 + j];
        *(float4*)&ber[j] = *(const float4*)&lnb[jc * 8 + j];
    }

    // ---- phase A: aggregate 8 nodes per warp ----
    for (int i = 0; i < 8; ++i) {
        int m = w * 8 + i;
        int n = base + m;
        int start = 0, end = 0;
        float2 ad = make_float2(0.f, 0.f);
        if (n < NN) {
            start = g_off[n];
            end = g_off[n + 1];
            ad = *(const float2*)(g_ad0 + n * 2);
        }
        float acc[8];
        #pragma unroll
        for (int j = 0; j < 8; ++j) acc[j] = 0.f;
        float d0 = 0.f, d1 = 0.f;

        for (int ii = start; ii < end; ii += 32) {
            int idx = ii + lane;
            int s = 0;
            float ex0 = 0.f, ex1 = 0.f;
            if (idx < end) {
                s = g_srcs[idx];
                float2 a = *(const float2*)(g_as0 + s * 2);
                float v0 = a.x + ad.x;  v0 = v0 > 0.f ? v0 : 0.2f * v0;
                float v1 = a.y + ad.y;  v1 = v1 > 0.f ? v1 : 0.2f * v1;
                ex0 = __expf(v0);
                ex1 = __expf(v1);
            }
            d0 += ex0;
            d1 += ex1;
            int cnt = min(32, end - ii);
            #pragma unroll 4
            for (int t = 0; t < cnt; t += 2) {
                int srcl = t + half;
                int sb = __shfl_sync(0xffffffffu, s, srcl);
                float e0 = __shfl_sync(0xffffffffu, ex0, srcl);
                float e1 = __shfl_sync(0xffffffffu, ex1, srcl);
                float exm = hsel ? e1 : e0;
                uint4 p = *(const uint4*)(g_h0h + sb * 128 + lc * 8);
                float2 f0 = __half22float2(*(__half2*)&p.x);
                float2 f1 = __half22float2(*(__half2*)&p.y);
                float2 f2 = __half22float2(*(__half2*)&p.z);
                float2 f3 = __half22float2(*(__half2*)&p.w);
                acc[0] += exm * f0.x;  acc[1] += exm * f0.y;
                acc[2] += exm * f1.x;  acc[3] += exm * f1.y;
                acc[4] += exm * f2.x;  acc[5] += exm * f2.y;
                acc[6] += exm * f3.x;  acc[7] += exm * f3.y;
            }
        }
        // combine the two in-flight halves; all 4 8-lane groups end up identical
        #pragma unroll
        for (int j = 0; j < 8; ++j) acc[j] += __shfl_xor_sync(0xffffffffu, acc[j], 16);
        #pragma unroll
        for (int o = 16; o > 0; o >>= 1) {
            d0 += __shfl_xor_sync(0xffffffffu, d0, o);
            d1 += __shfl_xor_sync(0xffffffffu, d1, o);
        }
        float inv0 = d0 > 0.f ? 1.f / d0 : 0.f;
        float inv1 = d1 > 0.f ? 1.f / d1 : 0.f;
        float invm = hsel ? inv1 : inv0;
        // head mean + b0: partner head cols live in lane lc^8
        float y[8];
        float s1 = 0.f, s2 = 0.f;
        #pragma unroll
        for (int j = 0; j < 8; ++j) {
            float an = acc[j] * invm;
            float pr = __shfl_xor_sync(0xffffffffu, an, 8);
            float yy = 0.5f * (an + pr) + b0r[j];
            y[j] = yy;
            s1 += yy;
            s2 += yy * yy;
        }
        // LN stats over the 8-lane group
        #pragma unroll
        for (int o = 4; o >= 1; o >>= 1) {
            s1 += __shfl_xor_sync(0xffffffffu, s1, o);
            s2 += __shfl_xor_sync(0xffffffffu, s2, o);
        }
        float mu = s1 * (1.f / 64.f);
        float var = s2 * (1.f / 64.f) - mu * mu;
        float rstd = rsqrtf(var + 1e-5f);
        if (lane < 8) {
            #pragma unroll
            for (int j = 0; j < 8; ++j) {
                float xn = (y[j] - mu) * rstd * gr[j] + ber[j];
                sYT[jc * 8 + j][m] = xn > 0.f ? xn : expm1f(xn);
            }
        }
    }
    __syncthreads();

    // ---- phase B: GEMM y @ W1 + alpha epilogue ----
    int c = tid & 15, rm = tid >> 4;
    float aSr[4], aDr[4];
    #pragma unroll
    for (int j = 0; j < 4; ++j) { aSr[j] = aS1[c * 4 + j]; aDr[j] = aD1[c * 4 + j]; }

    float facc[4][4];
    #pragma unroll
    for (int m = 0; m < 4; ++m)
        #pragma unroll
        for (int j = 0; j < 4; ++j) facc[m][j] = 0.f;

    #pragma unroll 8
    for (int k = 0; k < 64; ++k) {
        float4 wa = *(const float4*)&sW1s[k][c * 4];
        float4 xm4 = *(const float4*)&sYT[k][rm * 4];
        float xm[4] = {xm4.x, xm4.y, xm4.z, xm4.w};
        #pragma unroll
        for (int m = 0; m < 4; ++m) {
            facc[m][0] += xm[m] * wa.x;
            facc[m][1] += xm[m] * wa.y;
            facc[m][2] += xm[m] * wa.z;
            facc[m][3] += xm[m] * wa.w;
        }
    }

    #pragma unroll
    for (int m = 0; m < 4; ++m) {
        int n = base + rm * 4 + m;
        float vs = 0.f, vd = 0.f;
        #pragma unroll
        for (int j = 0; j < 4; ++j) { vs += facc[m][j] * aSr[j]; vd += facc[m][j] * aDr[j]; }
        #pragma unroll
        for (int o = 8; o >= 1; o >>= 1) {
            vs += __shfl_xor_sync(0xffffffffu, vs, o);
            vd += __shfl_xor_sync(0xffffffffu, vd, o);
        }
        if (n < NN) {
            __half2 p0 = __floats2half2_rn(facc[m][0], facc[m][1]);
            __half2 p1 = __floats2half2_rn(facc[m][2], facc[m][3]);
            uint2 u;
            u.x = h2u(p0);
            u.y = h2u(p1);
            *(uint2*)&g_h1h[n * 64 + c * 4] = u;
            if ((tid & 15) == 0) {
                g_as1[n] = vs;
                g_ad1[n] = vd;
            }
        }
    }
}

// ---------------- kagg1: layer1 aggregation, warp/dst, 4 edges in flight -----------
__global__ void __launch_bounds__(256) kagg1(float* __restrict__ out,
                                             const float* __restrict__ b1) {
    int w = (blockIdx.x * blockDim.x + threadIdx.x) >> 5;
    if (w >= NN) return;
    int lane = threadIdx.x & 31;
    int quad = lane >> 3;             // which of the 4 in-flight edges
    int lc = lane & 7;                // col group within edge
    int start = g_off[w], end = g_off[w + 1];
    float ad = g_ad1[w];
    float acc[8];
    #pragma unroll
    for (int j = 0; j < 8; ++j) acc[j] = 0.f;
    float den = 0.f;

    for (int i = start; i < end; i += 32) {
        int idx = i + lane;
        int s = 0;
        float ex = 0.f;
        if (idx < end) {
            s = g_srcs[idx];
            float v = g_as1[s] + ad;
            v = v > 0.f ? v : 0.2f * v;
            ex = __expf(v);
        }
        den += ex;
        int cnt = min(32, end - i);
        #pragma unroll 2
        for (int t = 0; t < cnt; t += 4) {
            int srcl = t + quad;
            int sb = __shfl_sync(0xffffffffu, s, srcl);
            float eb = __shfl_sync(0xffffffffu, ex, srcl);
            uint4 p = *(const uint4*)(g_h1h + sb * 64 + lc * 8);
            float2 f0 = __half22float2(*(__half2*)&p.x);
            float2 f1 = __half22float2(*(__half2*)&p.y);
            float2 f2 = __half22float2(*(__half2*)&p.z);
            float2 f3 = __half22float2(*(__half2*)&p.w);
            acc[0] += eb * f0.x;  acc[1] += eb * f0.y;
            acc[2] += eb * f1.x;  acc[3] += eb * f1.y;
            acc[4] += eb * f2.x;  acc[5] += eb * f2.y;
            acc[6] += eb * f3.x;  acc[7] += eb * f3.y;
        }
    }
    #pragma unroll
    for (int j = 0; j < 8; ++j) {
        acc[j] += __shfl_xor_sync(0xffffffffu, acc[j], 8);
        acc[j] += __shfl_xor_sync(0xffffffffu, acc[j], 16);
    }
    #pragma unroll
    for (int o = 16; o > 0; o >>= 1)
        den += __shfl_xor_sync(0xffffffffu, den, o);
    float inv = 1.0f / den;
    if (lane < 8) {
        float4 b4a = *(const float4*)&b1[lc * 8];
        float4 b4b = *(const float4*)&b1[lc * 8 + 4];
        float4 o0 = make_float4(acc[0] * inv + b4a.x, acc[1] * inv + b4a.y,
                                acc[2] * inv + b4a.z, acc[3] * inv + b4a.w);
        float4 o1 = make_float4(acc[4] * inv + b4b.x, acc[5] * inv + b4b.y,
                                acc[6] * inv + b4b.z, acc[7] * inv + b4b.w);
        *(float4*)(out + w * 64 + lc * 8) = o0;
        *(float4*)(out + w * 64 + lc * 8 + 4) = o1;
    }
}

// ---------------- launch -----------------------------------------------------------
extern "C" void kernel_launch(void* const* d_in, const int* in_sizes, int n_in,
                              void* d_out, int out_size) {
    const float* x      = (const float*)d_in[0];
    const int*   ei     = (const int*)  d_in[1];
    const float* emb    = (const float*)d_in[2];
    const float* W0     = (const float*)d_in[3];
    const float* a_src0 = (const float*)d_in[4];
    const float* a_dst0 = (const float*)d_in[5];
    const float* b0     = (const float*)d_in[6];
    const float* ln_g   = (const float*)d_in[7];
    const float* ln_b   = (const float*)d_in[8];
    const float* W1     = (const float*)d_in[9];
    const float* a_src1 = (const float*)d_in[10];
    const float* a_dst1 = (const float*)d_in[11];
    const float* b1     = (const float*)d_in[12];
    float* out = (float*)d_out;

    // CSR build (shared by both layers)
    void* cnt_addr = nullptr;
    cudaGetSymbolAddress(&cnt_addr, g_cnt);
    cudaMemsetAsync(cnt_addr, 0, NN * sizeof(int));
    khist<<<(NE + 255) / 256, 256>>>(ei);
    kscan<<<1, 1024>>>();
    kscatter<<<(NE + 255) / 256, 256>>>(ei);
    // layer 0 GEMM + logits
    k1g<<<(NN + G1_M - 1) / G1_M, 256>>>(x, emb, W0, a_src0, a_dst0);
    // layer 0 aggregation + LN + ELU + layer 1 GEMM + logits (fused)
    kfused<<<(NN + GF_M - 1) / GF_M, 256>>>(b0, ln_g, ln_b, W1, a_src1, a_dst1);
    // layer 1 aggregation -> output
    kagg1<<<(NN * 32 + 255) / 256, 256>>>(out, b1);
}